// round 5
// baseline (speedup 1.0000x reference)
#include <cuda_runtime.h>
#include <cuda_bf16.h>
#include <cstdint>

// LocalSelfAttention (bs=4,h=12,s=4096,d=64,block=64), sm_100 mma.sync path.
// CTA = 2 attention blocks, 128 threads; each warp computes an M=32 strip of one
// block (halves cross-warp K/V ldmatrix redundancy vs 4-warps-per-block).
// bf16 hi/lo 3x-split GEMMs (m16n8k16). Q direct LDG; K/V row-major XOR-swizzled
// smem via conflict-free STS.64, fragments via ldmatrix.x4 (trans for V).
// PV runs ntp-outer with pre-packed P fragments -> low register peak, early O stores.

#define OFF_KH 0          // K hi plane: 2 blocks x 64 rows x 128B
#define OFF_KL 16384
#define OFF_VH 32768
#define OFF_VL 49152
#define OFF_KB 65536      // 128 f32 key-side additive bias (2 blocks)
#define OFF_QM 66048      // 128 f32 query mask
#define SM_BYTES 66560

__device__ __forceinline__ uint32_t s2u(const void* p) {
    uint32_t a;
    asm("{ .reg .u64 t; cvta.to.shared.u64 t, %1; cvt.u32.u64 %0, t; }" : "=r"(a) : "l"(p));
    return a;
}
__device__ __forceinline__ uint32_t pk(float lo, float hi) {
    uint32_t r;
    asm("cvt.rn.bf16x2.f32 %0, %2, %1;" : "=r"(r) : "f"(lo), "f"(hi));
    return r;
}
__device__ __forceinline__ float bfr(float x) {
    return x - __bfloat162float(__float2bfloat16(x));
}
__device__ __forceinline__ void sts64(uint32_t a, uint32_t x, uint32_t y) {
    asm volatile("st.shared.v2.b32 [%0], {%1,%2};" :: "r"(a), "r"(x), "r"(y));
}
__device__ __forceinline__ void ldmx4(uint32_t a, uint32_t& r0, uint32_t& r1, uint32_t& r2, uint32_t& r3) {
    asm volatile("ldmatrix.sync.aligned.m8n8.x4.shared.b16 {%0,%1,%2,%3}, [%4];"
                 : "=r"(r0), "=r"(r1), "=r"(r2), "=r"(r3) : "r"(a));
}
__device__ __forceinline__ void ldmx4t(uint32_t a, uint32_t& r0, uint32_t& r1, uint32_t& r2, uint32_t& r3) {
    asm volatile("ldmatrix.sync.aligned.m8n8.x4.trans.shared.b16 {%0,%1,%2,%3}, [%4];"
                 : "=r"(r0), "=r"(r1), "=r"(r2), "=r"(r3) : "r"(a));
}
__device__ __forceinline__ void mma16(float* d,
                                      uint32_t a0, uint32_t a1, uint32_t a2, uint32_t a3,
                                      uint32_t b0, uint32_t b1) {
    asm volatile(
        "mma.sync.aligned.m16n8k16.row.col.f32.bf16.bf16.f32 "
        "{%0,%1,%2,%3}, {%4,%5,%6,%7}, {%8,%9}, {%0,%1,%2,%3};"
        : "+f"(d[0]), "+f"(d[1]), "+f"(d[2]), "+f"(d[3])
        : "r"(a0), "r"(a1), "r"(a2), "r"(a3), "r"(b0), "r"(b1));
}

__global__ void __launch_bounds__(128, 3) lsa5_kernel(
    const float* __restrict__ Qg_, const float* __restrict__ Kg_,
    const float* __restrict__ Vg_, const float* __restrict__ Mg_,
    float* __restrict__ Og_)
{
    extern __shared__ __align__(1024) char sm[];
    const uint32_t sb = s2u(sm);
    const int tid = threadIdx.x;
    const int bx = blockIdx.x;
    const size_t baseCTA = (size_t)bx * 8192;   // 2 blocks x 4096 floats

    // ---- mask staging (2 blocks) ----
    if (tid < 128) {
        int blk = 2 * bx + (tid >> 6);
        float m = Mg_[(size_t)(blk / 768) * 4096 + (size_t)((blk & 63) * 64 + (tid & 63))];
        ((float*)(sm + OFF_KB))[tid] = (m == 0.0f) ? -10000.0f : 0.0f;
        ((float*)(sm + OFF_QM))[tid] = m;
    }

    // ---- stage K,V (2 blocks) row-major bf16 hi/lo, XOR swizzle, conflict-free STS.64 ----
    const float4* Kg = (const float4*)(Kg_ + baseCTA);
    const float4* Vg = (const float4*)(Vg_ + baseCTA);
    #pragma unroll 4
    for (int it = 0; it < 16; it++) {
        int i = tid + it * 128;                  // 0..2047 float4s
        int r = (i >> 4) & 63;                   // row within block
        int bsel = i >> 10;                      // which block
        uint32_t cb = (uint32_t)((i & 15) * 8);  // byte col 0..120
        uint32_t sw = (uint32_t)(bsel * 8192 + r * 128) + (cb ^ (uint32_t)((r & 7) << 4));
        float4 k = Kg[i], v = Vg[i];
        sts64(sb + OFF_KH + sw, pk(k.x, k.y), pk(k.z, k.w));
        sts64(sb + OFF_KL + sw, pk(bfr(k.x), bfr(k.y)), pk(bfr(k.z), bfr(k.w)));
        sts64(sb + OFF_VH + sw, pk(v.x, v.y), pk(v.z, v.w));
        sts64(sb + OFF_VL + sw, pk(bfr(v.x), bfr(v.y)), pk(bfr(v.z), bfr(v.w)));
    }
    __syncthreads();

    const int w    = tid >> 5;
    const int lane = tid & 31;
    const int wb   = w >> 1;            // which block (0/1)
    const int ws   = w & 1;             // which 32-row strip
    const int g    = lane >> 2;
    const int t    = lane & 3;
    const int rl   = lane & 7;
    const int lg8  = (lane >> 3) & 1;
    const int lg16 = lane >> 4;
    const int mbase = ws * 32;
    const uint32_t wko = (uint32_t)(wb * 8192);

    float accS[2][8][4];
    #pragma unroll
    for (int mt = 0; mt < 2; mt++)
        #pragma unroll
        for (int nt = 0; nt < 8; nt++) {
            accS[mt][nt][0] = 0.f; accS[mt][nt][1] = 0.f;
            accS[mt][nt][2] = 0.f; accS[mt][nt][3] = 0.f;
        }

    // ---- S = Q K^T ----
    {
        const float* q0 = Qg_ + baseCTA + (size_t)(wb * 4096 + (mbase + g) * 64 + 2 * t);
        #pragma unroll
        for (int kt = 0; kt < 4; kt++) {
            uint32_t ah[2][4], al[2][4];
            #pragma unroll
            for (int mt = 0; mt < 2; mt++) {
                const float* qa = q0 + mt * 1024 + kt * 16;   // row mbase+mt*16+g
                const float* qb = qa + 512;                    // row +8
                float2 x0 = *(const float2*)qa;
                float2 x1 = *(const float2*)(qa + 8);
                float2 y0 = *(const float2*)qb;
                float2 y1 = *(const float2*)(qb + 8);
                ah[mt][0] = pk(x0.x, x0.y); ah[mt][1] = pk(y0.x, y0.y);
                ah[mt][2] = pk(x1.x, x1.y); ah[mt][3] = pk(y1.x, y1.y);
                al[mt][0] = pk(bfr(x0.x), bfr(x0.y)); al[mt][1] = pk(bfr(y0.x), bfr(y0.y));
                al[mt][2] = pk(bfr(x1.x), bfr(x1.y)); al[mt][3] = pk(bfr(y1.x), bfr(y1.y));
            }
            uint32_t cby = (uint32_t)(kt * 32 + lg8 * 16);
            #pragma unroll
            for (int ntp = 0; ntp < 4; ntp++) {
                int row = ntp * 16 + lg16 * 8 + rl;
                uint32_t adr = wko + (uint32_t)(row * 128) + (cby ^ (uint32_t)((row & 7) << 4));
                uint32_t bh0, bh1, bh2, bh3, bl0, bl1, bl2, bl3;
                ldmx4(sb + OFF_KH + adr, bh0, bh1, bh2, bh3);
                ldmx4(sb + OFF_KL + adr, bl0, bl1, bl2, bl3);
                #pragma unroll
                for (int mt = 0; mt < 2; mt++) {
                    mma16(accS[mt][2*ntp],   ah[mt][0], ah[mt][1], ah[mt][2], ah[mt][3], bh0, bh1);
                    mma16(accS[mt][2*ntp],   ah[mt][0], ah[mt][1], ah[mt][2], ah[mt][3], bl0, bl1);
                    mma16(accS[mt][2*ntp],   al[mt][0], al[mt][1], al[mt][2], al[mt][3], bh0, bh1);
                    mma16(accS[mt][2*ntp+1], ah[mt][0], ah[mt][1], ah[mt][2], ah[mt][3], bh2, bh3);
                    mma16(accS[mt][2*ntp+1], ah[mt][0], ah[mt][1], ah[mt][2], ah[mt][3], bl2, bl3);
                    mma16(accS[mt][2*ntp+1], al[mt][0], al[mt][1], al[mt][2], al[mt][3], bh2, bh3);
                }
            }
        }
    }

    // ---- softmax over 64 keys for 4 row-groups (g, g+8 per m-tile) ----
    const float* kb  = (const float*)(sm + OFF_KB) + wb * 64;
    const float* qmp = (const float*)(sm + OFF_QM) + wb * 64;
    float mx[4] = {-3.0e38f, -3.0e38f, -3.0e38f, -3.0e38f};
    #pragma unroll
    for (int mt = 0; mt < 2; mt++)
        #pragma unroll
        for (int nt = 0; nt < 8; nt++) {
            float2 kbv = *(const float2*)&kb[nt * 8 + 2 * t];
            accS[mt][nt][0] += kbv.x; accS[mt][nt][1] += kbv.y;
            accS[mt][nt][2] += kbv.x; accS[mt][nt][3] += kbv.y;
            mx[mt*2]   = fmaxf(mx[mt*2],   fmaxf(accS[mt][nt][0], accS[mt][nt][1]));
            mx[mt*2+1] = fmaxf(mx[mt*2+1], fmaxf(accS[mt][nt][2], accS[mt][nt][3]));
        }
    #pragma unroll
    for (int j = 0; j < 4; j++) {
        mx[j] = fmaxf(mx[j], __shfl_xor_sync(0xffffffffu, mx[j], 1));
        mx[j] = fmaxf(mx[j], __shfl_xor_sync(0xffffffffu, mx[j], 2));
    }
    float sum[4] = {0.f, 0.f, 0.f, 0.f};
    #pragma unroll
    for (int mt = 0; mt < 2; mt++)
        #pragma unroll
        for (int nt = 0; nt < 8; nt++) {
            accS[mt][nt][0] = __expf(accS[mt][nt][0] - mx[mt*2]);
            accS[mt][nt][1] = __expf(accS[mt][nt][1] - mx[mt*2]);
            accS[mt][nt][2] = __expf(accS[mt][nt][2] - mx[mt*2+1]);
            accS[mt][nt][3] = __expf(accS[mt][nt][3] - mx[mt*2+1]);
            sum[mt*2]   += accS[mt][nt][0] + accS[mt][nt][1];
            sum[mt*2+1] += accS[mt][nt][2] + accS[mt][nt][3];
        }
    float rs[4];
    #pragma unroll
    for (int j = 0; j < 4; j++) {
        sum[j] += __shfl_xor_sync(0xffffffffu, sum[j], 1);
        sum[j] += __shfl_xor_sync(0xffffffffu, sum[j], 2);
        int row = mbase + (j >> 1) * 16 + (j & 1) * 8 + g;
        rs[j] = (qmp[row] == 0.0f) ? 0.0f : (1.0f / sum[j]);
    }

    // ---- pre-pack P fragments (accS dies here) ----
    uint32_t ph[2][4][4], pl[2][4][4];
    #pragma unroll
    for (int mt = 0; mt < 2; mt++) {
        float rA = rs[mt*2], rB = rs[mt*2+1];
        #pragma unroll
        for (int k2 = 0; k2 < 4; k2++) {
            float v00 = accS[mt][2*k2][0]   * rA, v01 = accS[mt][2*k2][1]   * rA;
            float v10 = accS[mt][2*k2][2]   * rB, v11 = accS[mt][2*k2][3]   * rB;
            float v20 = accS[mt][2*k2+1][0] * rA, v21 = accS[mt][2*k2+1][1] * rA;
            float v30 = accS[mt][2*k2+1][2] * rB, v31 = accS[mt][2*k2+1][3] * rB;
            ph[mt][k2][0] = pk(v00, v01); ph[mt][k2][1] = pk(v10, v11);
            ph[mt][k2][2] = pk(v20, v21); ph[mt][k2][3] = pk(v30, v31);
            pl[mt][k2][0] = pk(bfr(v00), bfr(v01)); pl[mt][k2][1] = pk(bfr(v10), bfr(v11));
            pl[mt][k2][2] = pk(bfr(v20), bfr(v21)); pl[mt][k2][3] = pk(bfr(v30), bfr(v31));
        }
    }

    // ---- O = P V : ntp-outer, accO local per n-group, early stores ----
    float* Og = Og_ + baseCTA + wb * 4096;
    #pragma unroll
    for (int ntp = 0; ntp < 4; ntp++) {
        float accO[2][2][4];
        #pragma unroll
        for (int mt = 0; mt < 2; mt++)
            #pragma unroll
            for (int u = 0; u < 2; u++) {
                accO[mt][u][0] = 0.f; accO[mt][u][1] = 0.f;
                accO[mt][u][2] = 0.f; accO[mt][u][3] = 0.f;
            }
        uint32_t cby = (uint32_t)(ntp * 32 + lg16 * 16);
        #pragma unroll
        for (int k2 = 0; k2 < 4; k2++) {
            int row = k2 * 16 + lg8 * 8 + rl;
            uint32_t adr = wko + (uint32_t)(row * 128) + (cby ^ (uint32_t)((row & 7) << 4));
            uint32_t bh0, bh1, bh2, bh3, bl0, bl1, bl2, bl3;
            ldmx4t(sb + OFF_VH + adr, bh0, bh1, bh2, bh3);
            ldmx4t(sb + OFF_VL + adr, bl0, bl1, bl2, bl3);
            #pragma unroll
            for (int mt = 0; mt < 2; mt++) {
                mma16(accO[mt][0], ph[mt][k2][0], ph[mt][k2][1], ph[mt][k2][2], ph[mt][k2][3], bh0, bh1);
                mma16(accO[mt][0], ph[mt][k2][0], ph[mt][k2][1], ph[mt][k2][2], ph[mt][k2][3], bl0, bl1);
                mma16(accO[mt][0], pl[mt][k2][0], pl[mt][k2][1], pl[mt][k2][2], pl[mt][k2][3], bh0, bh1);
                mma16(accO[mt][1], ph[mt][k2][0], ph[mt][k2][1], ph[mt][k2][2], ph[mt][k2][3], bh2, bh3);
                mma16(accO[mt][1], ph[mt][k2][0], ph[mt][k2][1], ph[mt][k2][2], ph[mt][k2][3], bl2, bl3);
                mma16(accO[mt][1], pl[mt][k2][0], pl[mt][k2][1], pl[mt][k2][2], pl[mt][k2][3], bh2, bh3);
            }
        }
        #pragma unroll
        for (int mt = 0; mt < 2; mt++)
            #pragma unroll
            for (int u = 0; u < 2; u++) {
                int r0 = mbase + mt * 16 + g;
                int c = ntp * 16 + u * 8 + 2 * t;
                *(float2*)&Og[r0 * 64 + c]       = make_float2(accO[mt][u][0], accO[mt][u][1]);
                *(float2*)&Og[(r0 + 8) * 64 + c] = make_float2(accO[mt][u][2], accO[mt][u][3]);
            }
    }
}

extern "C" void kernel_launch(void* const* d_in, const int* in_sizes, int n_in,
                              void* d_out, int out_size) {
    const float* Q = (const float*)d_in[0];
    const float* K = (const float*)d_in[1];
    const float* V = (const float*)d_in[2];
    const float* M = (const float*)d_in[3];
    float* O = (float*)d_out;
    cudaFuncSetAttribute(lsa5_kernel, cudaFuncAttributeMaxDynamicSharedMemorySize, SM_BYTES);
    lsa5_kernel<<<1536, 128, SM_BYTES>>>(Q, K, V, M, O);
}

// round 6
// speedup vs baseline: 1.4769x; 1.4769x over previous
#include <cuda_runtime.h>
#include <cuda_fp16.h>
#include <cstdint>

// LocalSelfAttention (bs=4,h=12,s=4096,d=64,block=64), sm_100 mma.sync path.
// Per CTA: one 64x64 block, 4 warps (M=16 strips), 4 CTAs/SM.
// fp16 arithmetic: S = QK^T via 3-term hi/lo split (residual ~2^-24);
// O = PV via 2-term split (P hi/lo, V single rn-rounded fp16 plane).
// Q direct LDG fragments; K hi/lo + V single plane in XOR-swizzled smem,
// conflict-free STS.64 staging, fragments via ldmatrix.x4 (trans for V).

#define OFF_KH 0          // K hi plane: 64 rows x 128B
#define OFF_KL 8192       // K lo plane
#define OFF_VH 16384      // V plane (single)
#define OFF_KB 24576      // 64 f32 key-side additive bias
#define OFF_QM 24832      // 64 f32 query mask
#define SM_BYTES 25088

__device__ __forceinline__ uint32_t s2u(const void* p) {
    uint32_t a;
    asm("{ .reg .u64 t; cvta.to.shared.u64 t, %1; cvt.u32.u64 %0, t; }" : "=r"(a) : "l"(p));
    return a;
}
// pack two f32 -> f16x2 word: low half = first arg
__device__ __forceinline__ uint32_t pk(float lo, float hi) {
    uint32_t r;
    asm("cvt.rn.f16x2.f32 %0, %2, %1;" : "=r"(r) : "f"(lo), "f"(hi));
    return r;
}
__device__ __forceinline__ float hfr(float x) {   // residual x - f16(x)
    return x - __half2float(__float2half_rn(x));
}
__device__ __forceinline__ void sts64(uint32_t a, uint32_t x, uint32_t y) {
    asm volatile("st.shared.v2.b32 [%0], {%1,%2};" :: "r"(a), "r"(x), "r"(y));
}
__device__ __forceinline__ void ldmx4(uint32_t a, uint32_t& r0, uint32_t& r1, uint32_t& r2, uint32_t& r3) {
    asm volatile("ldmatrix.sync.aligned.m8n8.x4.shared.b16 {%0,%1,%2,%3}, [%4];"
                 : "=r"(r0), "=r"(r1), "=r"(r2), "=r"(r3) : "r"(a));
}
__device__ __forceinline__ void ldmx4t(uint32_t a, uint32_t& r0, uint32_t& r1, uint32_t& r2, uint32_t& r3) {
    asm volatile("ldmatrix.sync.aligned.m8n8.x4.trans.shared.b16 {%0,%1,%2,%3}, [%4];"
                 : "=r"(r0), "=r"(r1), "=r"(r2), "=r"(r3) : "r"(a));
}
__device__ __forceinline__ void mma16(float* d,
                                      uint32_t a0, uint32_t a1, uint32_t a2, uint32_t a3,
                                      uint32_t b0, uint32_t b1) {
    asm volatile(
        "mma.sync.aligned.m16n8k16.row.col.f32.f16.f16.f32 "
        "{%0,%1,%2,%3}, {%4,%5,%6,%7}, {%8,%9}, {%0,%1,%2,%3};"
        : "+f"(d[0]), "+f"(d[1]), "+f"(d[2]), "+f"(d[3])
        : "r"(a0), "r"(a1), "r"(a2), "r"(a3), "r"(b0), "r"(b1));
}

__global__ void __launch_bounds__(128, 4) lsa6_kernel(
    const float* __restrict__ Qg_, const float* __restrict__ Kg_,
    const float* __restrict__ Vg_, const float* __restrict__ Mg_,
    float* __restrict__ Og_)
{
    extern __shared__ __align__(1024) char sm[];
    const uint32_t sb = s2u(sm);
    const int tid = threadIdx.x;
    const int blk = blockIdx.x;
    const size_t base = (size_t)blk * 4096;

    // ---- mask staging ----
    if (tid < 64) {
        int b  = blk / 768;
        int nb = blk & 63;
        float m = Mg_[(size_t)b * 4096 + (size_t)(nb * 64 + tid)];
        *(float*)(sm + OFF_KB + tid * 4) = (m == 0.0f) ? -10000.0f : 0.0f;
        *(float*)(sm + OFF_QM + tid * 4) = m;
    }

    // ---- stage K (hi/lo) and V (single) fp16, XOR swizzle, conflict-free STS.64 ----
    const float4* Kg = (const float4*)(Kg_ + base);
    const float4* Vg = (const float4*)(Vg_ + base);
    #pragma unroll
    for (int it = 0; it < 8; it++) {
        int i = tid + it * 128;                  // 0..1023
        int r = i >> 4;                          // row 0..63
        uint32_t cb = (uint32_t)((i & 15) * 8);  // byte col 0..120
        uint32_t sw = (uint32_t)(r * 128) + (cb ^ (uint32_t)((r & 7) << 4));
        float4 k = Kg[i], v = Vg[i];
        sts64(sb + OFF_KH + sw, pk(k.x, k.y), pk(k.z, k.w));
        sts64(sb + OFF_KL + sw, pk(hfr(k.x), hfr(k.y)), pk(hfr(k.z), hfr(k.w)));
        sts64(sb + OFF_VH + sw, pk(v.x, v.y), pk(v.z, v.w));
    }
    __syncthreads();

    const int w    = tid >> 5;
    const int lane = tid & 31;
    const int g    = lane >> 2;
    const int t    = lane & 3;
    const int mb   = w * 16;
    const int rl   = lane & 7;
    const int lg8  = (lane >> 3) & 1;
    const int lg16 = lane >> 4;

    float acc[8][4];
    #pragma unroll
    for (int nt = 0; nt < 8; nt++) {
        acc[nt][0] = 0.f; acc[nt][1] = 0.f; acc[nt][2] = 0.f; acc[nt][3] = 0.f;
    }

    // ---- S = Q K^T : 3-term fp16 split; Q direct from global, K via ldmatrix ----
    {
        const float* qr0 = Qg_ + base + (size_t)((mb + g) * 64 + 2 * t);
        const float* qr1 = qr0 + 8 * 64;
        #pragma unroll
        for (int kt = 0; kt < 4; kt++) {
            float2 q00 = *(const float2*)(qr0 + kt * 16);
            float2 q01 = *(const float2*)(qr0 + kt * 16 + 8);
            float2 q10 = *(const float2*)(qr1 + kt * 16);
            float2 q11 = *(const float2*)(qr1 + kt * 16 + 8);
            uint32_t a0h = pk(q00.x, q00.y), a1h = pk(q10.x, q10.y);
            uint32_t a2h = pk(q01.x, q01.y), a3h = pk(q11.x, q11.y);
            uint32_t a0l = pk(hfr(q00.x), hfr(q00.y)), a1l = pk(hfr(q10.x), hfr(q10.y));
            uint32_t a2l = pk(hfr(q01.x), hfr(q01.y)), a3l = pk(hfr(q11.x), hfr(q11.y));
            uint32_t cbyte = (uint32_t)(kt * 32 + lg8 * 16);
            #pragma unroll
            for (int ntp = 0; ntp < 4; ntp++) {
                int row = ntp * 16 + lg16 * 8 + rl;
                uint32_t addr = (uint32_t)(row * 128) + (cbyte ^ (uint32_t)((row & 7) << 4));
                uint32_t bh0, bh1, bh2, bh3, bl0, bl1, bl2, bl3;
                ldmx4(sb + OFF_KH + addr, bh0, bh1, bh2, bh3);
                ldmx4(sb + OFF_KL + addr, bl0, bl1, bl2, bl3);
                mma16(acc[2*ntp],   a0h, a1h, a2h, a3h, bh0, bh1);
                mma16(acc[2*ntp],   a0h, a1h, a2h, a3h, bl0, bl1);
                mma16(acc[2*ntp],   a0l, a1l, a2l, a3l, bh0, bh1);
                mma16(acc[2*ntp+1], a0h, a1h, a2h, a3h, bh2, bh3);
                mma16(acc[2*ntp+1], a0h, a1h, a2h, a3h, bl2, bl3);
                mma16(acc[2*ntp+1], a0l, a1l, a2l, a3l, bh2, bh3);
            }
        }
    }

    // ---- softmax (rows in-warp, quad shuffles) ----
    const float* kbias = (const float*)(sm + OFF_KB);
    const float* qm    = (const float*)(sm + OFF_QM);
    float m0 = -3.0e38f, m1 = -3.0e38f;
    #pragma unroll
    for (int nt = 0; nt < 8; nt++) {
        float2 kbv = *(const float2*)&kbias[nt * 8 + 2 * t];
        acc[nt][0] += kbv.x; acc[nt][1] += kbv.y;
        acc[nt][2] += kbv.x; acc[nt][3] += kbv.y;
        m0 = fmaxf(m0, fmaxf(acc[nt][0], acc[nt][1]));
        m1 = fmaxf(m1, fmaxf(acc[nt][2], acc[nt][3]));
    }
    m0 = fmaxf(m0, __shfl_xor_sync(0xffffffffu, m0, 1));
    m0 = fmaxf(m0, __shfl_xor_sync(0xffffffffu, m0, 2));
    m1 = fmaxf(m1, __shfl_xor_sync(0xffffffffu, m1, 1));
    m1 = fmaxf(m1, __shfl_xor_sync(0xffffffffu, m1, 2));
    float s0 = 0.f, s1 = 0.f;
    #pragma unroll
    for (int nt = 0; nt < 8; nt++) {
        acc[nt][0] = __expf(acc[nt][0] - m0);
        acc[nt][1] = __expf(acc[nt][1] - m0);
        acc[nt][2] = __expf(acc[nt][2] - m1);
        acc[nt][3] = __expf(acc[nt][3] - m1);
        s0 += acc[nt][0] + acc[nt][1];
        s1 += acc[nt][2] + acc[nt][3];
    }
    s0 += __shfl_xor_sync(0xffffffffu, s0, 1);
    s0 += __shfl_xor_sync(0xffffffffu, s0, 2);
    s1 += __shfl_xor_sync(0xffffffffu, s1, 1);
    s1 += __shfl_xor_sync(0xffffffffu, s1, 2);
    float r0 = (qm[mb + g]     == 0.0f) ? 0.0f : (1.0f / s0);
    float r1 = (qm[mb + g + 8] == 0.0f) ? 0.0f : (1.0f / s1);

    // ---- O = P V : 2-term (P hi/lo from registers, V single plane via ldmatrix.trans) ----
    float accO[8][4];
    #pragma unroll
    for (int nt = 0; nt < 8; nt++) {
        accO[nt][0] = 0.f; accO[nt][1] = 0.f; accO[nt][2] = 0.f; accO[nt][3] = 0.f;
    }
    #pragma unroll
    for (int kt = 0; kt < 4; kt++) {
        float s00 = acc[2*kt][0]   * r0, s01 = acc[2*kt][1]   * r0;
        float s10 = acc[2*kt][2]   * r1, s11 = acc[2*kt][3]   * r1;
        float s20 = acc[2*kt+1][0] * r0, s21 = acc[2*kt+1][1] * r0;
        float s30 = acc[2*kt+1][2] * r1, s31 = acc[2*kt+1][3] * r1;
        uint32_t a0h = pk(s00, s01), a1h = pk(s10, s11);
        uint32_t a2h = pk(s20, s21), a3h = pk(s30, s31);
        uint32_t a0l = pk(hfr(s00), hfr(s01)), a1l = pk(hfr(s10), hfr(s11));
        uint32_t a2l = pk(hfr(s20), hfr(s21)), a3l = pk(hfr(s30), hfr(s31));
        int vrow = kt * 16 + lg8 * 8 + rl;
        uint32_t vbase = (uint32_t)(vrow * 128);
        uint32_t vswx  = (uint32_t)((vrow & 7) << 4);
        #pragma unroll
        for (int ntp = 0; ntp < 4; ntp++) {
            uint32_t cbyte = (uint32_t)(ntp * 32 + lg16 * 16);
            uint32_t addr = vbase + (cbyte ^ vswx);
            uint32_t bh0, bh1, bh2, bh3;
            ldmx4t(sb + OFF_VH + addr, bh0, bh1, bh2, bh3);
            mma16(accO[2*ntp],   a0h, a1h, a2h, a3h, bh0, bh1);
            mma16(accO[2*ntp],   a0l, a1l, a2l, a3l, bh0, bh1);
            mma16(accO[2*ntp+1], a0h, a1h, a2h, a3h, bh2, bh3);
            mma16(accO[2*ntp+1], a0l, a1l, a2l, a3l, bh2, bh3);
        }
    }

    // ---- store O (sector-aligned float2) ----
    float* Og = Og_ + base;
    #pragma unroll
    for (int nt = 0; nt < 8; nt++) {
        *(float2*)&Og[(mb + g)     * 64 + nt * 8 + 2 * t] = make_float2(accO[nt][0], accO[nt][1]);
        *(float2*)&Og[(mb + g + 8) * 64 + nt * 8 + 2 * t] = make_float2(accO[nt][2], accO[nt][3]);
    }
}

extern "C" void kernel_launch(void* const* d_in, const int* in_sizes, int n_in,
                              void* d_out, int out_size) {
    const float* Q = (const float*)d_in[0];
    const float* K = (const float*)d_in[1];
    const float* V = (const float*)d_in[2];
    const float* M = (const float*)d_in[3];
    float* O = (float*)d_out;
    cudaFuncSetAttribute(lsa6_kernel, cudaFuncAttributeMaxDynamicSharedMemorySize, SM_BYTES);
    lsa6_kernel<<<3072, 128, SM_BYTES>>>(Q, K, V, M, O);
}